// round 12
// baseline (speedup 1.0000x reference)
#include <cuda_runtime.h>
#include <cuda_bf16.h>
#include <math.h>
#include <stdint.h>

// Problem dims
#define B_   1024
#define H1   500
#define IN_  784
#define NOUT 10
#define T_   100
#define NP   512

// pass-0 (integer class-0) / pass-1 (5-slot corrections) padded K
#define K0P1 832     // 784 -> 13*64
#define K1P1 3968    // 784*5=3920 -> 62*64
#define K0P2 512     // 500 -> 8*64
#define K1P2 2560    // 500*5=2500 -> 40*64

// ---------------- device scratch ----------------
__device__ __align__(16) __nv_bfloat16 g_p0a1[(size_t)B_ * K0P1];
__device__ __align__(16) __nv_bfloat16 g_p0w1[(size_t)NP * K0P1];
__device__ __align__(16) __nv_bfloat16 g_p1a1[(size_t)B_ * K1P1];
__device__ __align__(16) __nv_bfloat16 g_p1w1[(size_t)NP * K1P1];
__device__ __align__(16) __nv_bfloat16 g_p0a2[(size_t)B_ * K0P2];
__device__ __align__(16) __nv_bfloat16 g_p0w2[(size_t)NP * K0P2];
__device__ __align__(16) __nv_bfloat16 g_p1a2[(size_t)B_ * K1P2];
__device__ __align__(16) __nv_bfloat16 g_p1w2[(size_t)NP * K1P2];
__device__ float g_sa1[B_], g_sw1[NP], g_sa2[B_], g_sw2[NP];
__device__ float g_h[B_ * H1];
__device__ float g_drive[B_ * H1];
__device__ float g_cf[T_];

// ---------------- helpers ----------------
#define SW128(o) ((o) ^ (((o) >> 3) & 0x70))

__device__ __forceinline__ uint32_t smem_u32(const void* p) {
    uint32_t a;
    asm("{ .reg .u64 t; cvta.to.shared.u64 t, %1; cvt.u32.u64 %0, t; }"
        : "=r"(a) : "l"(p));
    return a;
}
__device__ __forceinline__ void cp_async16(uint32_t dst, const void* src) {
    asm volatile("cp.async.cg.shared.global [%0], [%1], 16;"
                 :: "r"(dst), "l"(src));
}
#define CP_COMMIT()  asm volatile("cp.async.commit_group;" ::: "memory")
#define CP_WAIT(n)   asm volatile("cp.async.wait_group %0;" :: "n"(n) : "memory")

__device__ __forceinline__ void ldm_x4(uint32_t& r0, uint32_t& r1,
                                       uint32_t& r2, uint32_t& r3, uint32_t addr) {
    asm volatile("ldmatrix.sync.aligned.m8n8.x4.shared.b16 {%0,%1,%2,%3}, [%4];"
                 : "=r"(r0), "=r"(r1), "=r"(r2), "=r"(r3) : "r"(addr));
}
__device__ __forceinline__ void ldm_x2(uint32_t& r0, uint32_t& r1, uint32_t addr) {
    asm volatile("ldmatrix.sync.aligned.m8n8.x2.shared.b16 {%0,%1}, [%2];"
                 : "=r"(r0), "=r"(r1) : "r"(addr));
}
__device__ __forceinline__ void mma16816(float* c, const uint32_t* a, const uint32_t* b) {
    asm volatile("mma.sync.aligned.m16n8k16.row.col.f32.bf16.bf16.f32 "
                 "{%0,%1,%2,%3}, {%4,%5,%6,%7}, {%8,%9}, {%0,%1,%2,%3};"
                 : "+f"(c[0]), "+f"(c[1]), "+f"(c[2]), "+f"(c[3])
                 : "r"(a[0]), "r"(a[1]), "r"(a[2]), "r"(a[3]),
                   "r"(b[0]), "r"(b[1]));
}

// ---------------- integer limb extraction (proven exact) --------------------
__device__ __forceinline__ void limbs_of(float a, float qs,
                                         float& A0, float& A1, float& A2) {
    const float q = a * qs;
    A0 = rintf(q);
    const float r1 = q - A0;
    const float t1 = r1 * 256.0f;
    A1 = rintf(t1);
    const float r2 = t1 - A1;
    A2 = rintf(r2 * 256.0f);
}

// Row converter (runtime dims). isA -> slots [L0,L1,L1,L0,L2], else [L1,L0,L1,L2,L0].
__device__ void conv_row_body(const float* __restrict__ gsrc, int valid,
                              int KD, int K0P, int K1P, bool isA,
                              __nv_bfloat16* __restrict__ p0,
                              __nv_bfloat16* __restrict__ p1,
                              float* __restrict__ sarr, int ridx,
                              float* __restrict__ srow, float* __restrict__ red) {
    const int tid = threadIdx.x;  // 256
    float mx = 0.0f;
    for (int k = tid; k < KD; k += 256) {
        const float a = valid ? gsrc[k] : 0.0f;
        srow[k] = a;
        mx = fmaxf(mx, fabsf(a));
    }
    red[tid] = mx;
    __syncthreads();
    for (int s = 128; s; s >>= 1) {
        if (tid < s) red[tid] = fmaxf(red[tid], red[tid + s]);
        __syncthreads();
    }
    const float rm = red[0];
    int e = 0;
    if (rm > 0.0f) frexpf(rm, &e);
    if (tid == 0) sarr[ridx] = ldexpf(1.0f, e - 8);
    const float qs = ldexpf(1.0f, 8 - e);
    const float s0 = ldexpf(1.0f, e - 8);
    const float s1 = ldexpf(1.0f, e - 16);
    const float s2 = ldexpf(1.0f, e - 24);

    for (int k = tid; k < K0P; k += 256) {
        float A0v = 0.0f;
        if (k < KD) A0v = rintf(srow[k] * qs);
        p0[k] = __float2bfloat16(A0v);
    }
    const int lim = 5 * KD;
    for (int c = tid; c < K1P; c += 256) {      // fully coalesced 2B stores
        __nv_bfloat16 v = __float2bfloat16(0.0f);
        if (c < lim) {
            const int k = c / 5, r = c - 5 * k;
            float A0, A1, A2;
            limbs_of(srow[k], qs, A0, A1, A2);
            const __nv_bfloat16 L0 = __float2bfloat16(A0 * s0);
            const __nv_bfloat16 L1 = __float2bfloat16(A1 * s1);
            const __nv_bfloat16 L2 = __float2bfloat16(A2 * s2);
            if (isA) v = (r == 0 || r == 3) ? L0 : (r == 4 ? L2 : L1);
            else     v = (r == 1 || r == 4) ? L0 : (r == 3 ? L2 : L1);
        }
        p1[c] = v;
    }
}

// Merged input conversions: x rows, w1 rows, w2 rows, + cf[] block.
__global__ void __launch_bounds__(256)
k_convIn(const float* __restrict__ x, const float* __restrict__ w1,
         const float* __restrict__ w2) {
    __shared__ float srow[IN_];
    __shared__ float red[256];
    const int b = blockIdx.x;
    if (b < B_) {
        conv_row_body(x + (long)b * IN_, 1, IN_, K0P1, K1P1, true,
                      g_p0a1 + (long)b * K0P1, g_p1a1 + (long)b * K1P1,
                      g_sa1, b, srow, red);
    } else if (b < B_ + NP) {
        const int n = b - B_;
        conv_row_body(w1 + (long)n * IN_, n < H1, IN_, K0P1, K1P1, false,
                      g_p0w1 + (long)n * K0P1, g_p1w1 + (long)n * K1P1,
                      g_sw1, n, srow, red);
    } else if (b < B_ + 2 * NP) {
        const int n = b - B_ - NP;
        conv_row_body(w2 + (long)n * H1, n < H1, H1, K0P2, K1P2, false,
                      g_p0w2 + (long)n * K0P2, g_p1w2 + (long)n * K1P2,
                      g_sw2, n, srow, red);
    } else {
        if (threadIdx.x < T_) {        // cf[] in fp64 closed form
            const double r = 0.77880078307140487;   // exp(-1/4)
            const double q = 0.36787944117144233;   // exp(-1)
            const double tp1 = (double)(threadIdx.x + 1);
            const double rp = exp(-0.25 * tp1);
            const double qp = exp(-tp1);
            const double c = (r * (1.0 - rp) / (1.0 - r)
                            - q * (1.0 - qp) / (1.0 - q)) / (r - q);
            g_cf[threadIdx.x] = (float)c;
        }
    }
}

__global__ void __launch_bounds__(256) k_cA2() {
    __shared__ float srow[H1];
    __shared__ float red[256];
    const int m = blockIdx.x;
    conv_row_body(g_h + (long)m * H1, 1, H1, K0P2, K1P2, true,
                  g_p0a2 + (long)m * K0P2, g_p1a2 + (long)m * K1P2,
                  g_sa2, m, srow, red);
}

// ---------------- HMMA: unified 2-pass stream, 4-stage cp.async pipeline ----
__device__ __forceinline__ void issue_chunk2(const __nv_bfloat16* __restrict__ A,
                                             const __nv_bfloat16* __restrict__ B,
                                             int ks, long koff, int m0, int n0,
                                             uint32_t stage, int tid) {
#pragma unroll
    for (int i = 0; i < 2; i++) {
        const int e = tid + 256 * i;           // 0..511
        const int row = e >> 3, c8 = e & 7;
        const uint32_t dst = SW128((uint32_t)(row * 128 + c8 * 16));
        cp_async16(stage + dst,        A + (long)(m0 + row) * ks + koff + c8 * 8);
        cp_async16(stage + 8192 + dst, B + (long)(n0 + row) * ks + koff + c8 * 8);
    }
}

// MODE 1: layer1 (relu -> g_h), MODE 2: layer2 (sigmoid -> g_drive)
template<int MODE>
__global__ void __launch_bounds__(256) k_mma(const float* __restrict__ bias) {
    extern __shared__ char sm[];               // 4 stages x 16KB = 64KB dynamic
    const int tid = threadIdx.x;
    const int warp = tid >> 5, lane = tid & 31;
    const int wm = warp & 3, wn = warp >> 2;   // 4 M-warps x 2 N-warps
    const int m0 = blockIdx.y * 64, n0 = blockIdx.x * 64;

    const __nv_bfloat16 *A0g, *B0g, *A1g, *B1g;
    const float *sa, *sw;
    int K0, K1, NC0, NC1;
    if (MODE == 1) {
        A0g = g_p0a1; B0g = g_p0w1; A1g = g_p1a1; B1g = g_p1w1;
        sa = g_sa1; sw = g_sw1; K0 = K0P1; K1 = K1P1; NC0 = 13; NC1 = 62;
    } else {
        A0g = g_p0a2; B0g = g_p0w2; A1g = g_p1a2; B1g = g_p1w2;
        sa = g_sa2; sw = g_sw2; K0 = K0P2; K1 = K1P2; NC0 = 8; NC1 = 40;
    }
    const int NCT = NC0 + NC1;

    float S0[16], S1[16];
#pragma unroll
    for (int i = 0; i < 16; i++) { S0[i] = 0.0f; S1[i] = 0.0f; }

    const uint32_t smb = smem_u32(sm);

    // prologue: chunks 0..2 (NCT >= 3 always)
#pragma unroll
    for (int p = 0; p < 3; p++) {
        if (p < NC0) issue_chunk2(A0g, B0g, K0, (long)p * 64, m0, n0,
                                  smb + p * 16384, tid);
        else         issue_chunk2(A1g, B1g, K1, (long)(p - NC0) * 64, m0, n0,
                                  smb + p * 16384, tid);
        CP_COMMIT();
    }

    for (int c = 0; c < NCT; c++) {
        CP_WAIT(2);                 // with always-commit below, guarantees chunk c
        __syncthreads();            // all warps done with stage (c-1)&3
        if (c + 3 < NCT) {          // refill stage (c+3)&3 == (c-1)&3
            const int p = c + 3;
            if (p < NC0) issue_chunk2(A0g, B0g, K0, (long)p * 64, m0, n0,
                                      smb + ((p & 3) * 16384), tid);
            else         issue_chunk2(A1g, B1g, K1, (long)(p - NC0) * 64, m0, n0,
                                      smb + ((p & 3) * 16384), tid);
        }
        CP_COMMIT();                // ALWAYS commit (empty near tail) — keeps
                                    // wait_group(2) pointing at chunk c's group
        const uint32_t sA = smb + (c & 3) * 16384;
        const uint32_t sB = sA + 8192;

        float acc[4][4];
#pragma unroll
        for (int b = 0; b < 4; b++)
#pragma unroll
            for (int e2 = 0; e2 < 4; e2++) acc[b][e2] = 0.0f;

#pragma unroll
        for (int k16 = 0; k16 < 4; k16++) {
            uint32_t af[4], bf[4][2];
            const int rowa = wm * 16 + (lane & 15);
            const uint32_t kcol = (uint32_t)(k16 * 32 + (lane >> 4) * 16);
            ldm_x4(af[0], af[1], af[2], af[3],
                   sA + SW128((uint32_t)(rowa * 128) + kcol));
            const uint32_t kcolb = (uint32_t)(k16 * 32 + ((lane >> 3) & 1) * 16);
#pragma unroll
            for (int nt = 0; nt < 4; nt++) {
                const int rowb = wn * 32 + nt * 8 + (lane & 7);
                ldm_x2(bf[nt][0], bf[nt][1],
                       sB + SW128((uint32_t)(rowb * 128) + kcolb));
            }
#pragma unroll
            for (int nt = 0; nt < 4; nt++)
                mma16816(acc[nt], af, bf[nt]);
        }
        // drain chunk partial with RN adds (order identical to R11)
        if (c < NC0) {
#pragma unroll
            for (int b = 0; b < 4; b++)
#pragma unroll
                for (int e2 = 0; e2 < 4; e2++)
                    S0[b * 4 + e2] = __fadd_rn(S0[b * 4 + e2], acc[b][e2]);
        } else {
#pragma unroll
            for (int b = 0; b < 4; b++)
#pragma unroll
                for (int e2 = 0; e2 < 4; e2++)
                    S1[b * 4 + e2] = __fadd_rn(S1[b * 4 + e2], acc[b][e2]);
        }
    }

    // epilogue: v = RN(S0 * 2^(ea+eb-16)) + S1 + bias
#pragma unroll
    for (int nt = 0; nt < 4; nt++) {
        const int gn = n0 + wn * 32 + nt * 8 + (lane & 3) * 2;
#pragma unroll
        for (int rr = 0; rr < 2; rr++) {
            const int m = m0 + wm * 16 + (lane >> 2) + rr * 8;
            const float sam = sa[m];
#pragma unroll
            for (int jj = 0; jj < 2; jj++) {
                const int n = gn + jj;
                if (n >= H1) continue;
                const float sab = sam * sw[n];
                const int idx = nt * 4 + rr * 2 + jj;
                float v = __fadd_rn(__fmul_rn(S0[idx], sab), S1[idx]);
                v = v + bias[n];
                if (MODE == 1) {
                    g_h[(long)m * H1 + n] = fmaxf(v, 0.0f);
                } else {
                    if (v >= 0.0f) v = 1.0f / (1.0f + expf(-v));
                    else { const float e = expf(v); v = e / (1.0f + e); }
                    g_drive[(long)m * H1 + n] = v;
                }
            }
        }
    }
}

// ---------------- fused gemm3 + LIF scan (proven exact) ----------------
__global__ void __launch_bounds__(256, 8)
k_fused3(const float* __restrict__ w3,
         const float* __restrict__ b3,
         float* __restrict__ out) {
    const int m = blockIdx.x;
    __shared__ float row[H1];
    __shared__ float part[250];
    __shared__ float cf[T_];
    __shared__ unsigned sbits[NOUT][4];

    const int tid = threadIdx.x;  // 256
    for (int k = tid; k < H1; k += 256) row[k] = g_drive[m * H1 + k];
    if (tid < T_) cf[tid] = g_cf[tid];
    __syncthreads();

    if (tid < 250) {
        const int n = tid / 25;
        const int ks = (tid % 25) * 20;
        float s = 0.0f;
#pragma unroll
        for (int k = 0; k < 20; k++)
            s = fmaf(row[ks + k], w3[n * H1 + ks + k], s);
        part[tid] = s;
    }
    __syncthreads();

    if (tid < NOUT) {
        float u = 0.0f;
#pragma unroll
        for (int p = 0; p < 25; p++) u += part[tid * 25 + p];

        const float bb = b3[tid];
        const int SIGB = __float_as_int(0.77880078307140487f);
        float v = 0.0f;
        float f = __int_as_float(SIGB);
        unsigned sb0 = 0, sb1 = 0, sb2 = 0, sb3v = 0;
#pragma unroll
        for (int t = 0; t < T_; t++) {
            const float cur = __fadd_rn(__fmul_rn(cf[t], u), bb);
            v = __fadd_rn(__fmul_rn(f, v), cur);
            const int tb = __float_as_int(__fadd_rn(v, -1.0f));
            const int smask = tb >> 31;
            f = __int_as_float(SIGB & smask);
            const unsigned bit = (unsigned)(~smask) & 1u;
            if (t < 32)       sb0 |= bit << t;
            else if (t < 64)  sb1 |= bit << (t - 32);
            else if (t < 96)  sb2 |= bit << (t - 64);
            else              sb3v |= bit << (t - 96);
        }
        sbits[tid][0] = sb0; sbits[tid][1] = sb1;
        sbits[tid][2] = sb2; sbits[tid][3] = sb3v;
    }
    __syncthreads();

    float* oblk = out + (size_t)m * NOUT * T_;
#pragma unroll
    for (int i = tid; i < NOUT * T_; i += 256) {
        const int n = i / T_;
        const int t = i - n * T_;
        const unsigned w = sbits[n][t >> 5];
        oblk[i] = (float)((w >> (t & 31)) & 1u);
    }
}

// ---------------- launch ----------------
extern "C" void kernel_launch(void* const* d_in, const int* in_sizes, int n_in,
                              void* d_out, int out_size) {
    const float* x  = (const float*)d_in[0];
    const float* w1 = (const float*)d_in[1];
    const float* b1 = (const float*)d_in[2];
    const float* w2 = (const float*)d_in[3];
    const float* b2 = (const float*)d_in[4];
    const float* w3 = (const float*)d_in[5];
    const float* b3 = (const float*)d_in[6];
    float* out = (float*)d_out;

    cudaFuncSetAttribute(k_mma<1>, cudaFuncAttributeMaxDynamicSharedMemorySize, 65536);
    cudaFuncSetAttribute(k_mma<2>, cudaFuncAttributeMaxDynamicSharedMemorySize, 65536);

    k_convIn<<<B_ + 2 * NP + 1, 256>>>(x, w1, w2);

    dim3 grid(NP / 64, B_ / 64);               // (8, 16) = 128 CTAs
    k_mma<1><<<grid, 256, 65536>>>(b1);
    k_cA2<<<B_, 256>>>();
    k_mma<2><<<grid, 256, 65536>>>(b2);

    k_fused3<<<B_, 256>>>(w3, b3, out);
}

// round 13
// speedup vs baseline: 1.2730x; 1.2730x over previous
#include <cuda_runtime.h>
#include <cuda_bf16.h>
#include <math.h>
#include <stdint.h>

// Problem dims
#define B_   1024
#define H1   500
#define IN_  784
#define NOUT 10
#define T_   100
#define NP   512

// pass-0 (integer class-0) padded K; pass-1 is group-major: K1P = 5*K0P
#define K0P1 832     // 784 -> 13*64
#define K1P1 4160    // 5*832 -> 65*64
#define K0P2 512     // 500 -> 8*64
#define K1P2 2560    // 5*512 -> 40*64

// ---------------- device scratch ----------------
__device__ __align__(16) __nv_bfloat16 g_p0a1[(size_t)B_ * K0P1];
__device__ __align__(16) __nv_bfloat16 g_p0w1[(size_t)NP * K0P1];
__device__ __align__(16) __nv_bfloat16 g_p1a1[(size_t)B_ * K1P1];
__device__ __align__(16) __nv_bfloat16 g_p1w1[(size_t)NP * K1P1];
__device__ __align__(16) __nv_bfloat16 g_p0a2[(size_t)B_ * K0P2];
__device__ __align__(16) __nv_bfloat16 g_p0w2[(size_t)NP * K0P2];
__device__ __align__(16) __nv_bfloat16 g_p1a2[(size_t)B_ * K1P2];
__device__ __align__(16) __nv_bfloat16 g_p1w2[(size_t)NP * K1P2];
__device__ float g_sa1[B_], g_sw1[NP], g_sa2[B_], g_sw2[NP];
__device__ float g_h[B_ * H1];
__device__ float g_drive[B_ * H1];
__device__ float g_cf[T_];

// ---------------- helpers ----------------
#define SW128(o) ((o) ^ (((o) >> 3) & 0x70))

__device__ __forceinline__ uint32_t smem_u32(const void* p) {
    uint32_t a;
    asm("{ .reg .u64 t; cvta.to.shared.u64 t, %1; cvt.u32.u64 %0, t; }"
        : "=r"(a) : "l"(p));
    return a;
}
__device__ __forceinline__ void cp_async16(uint32_t dst, const void* src) {
    asm volatile("cp.async.cg.shared.global [%0], [%1], 16;"
                 :: "r"(dst), "l"(src));
}
#define CP_COMMIT()  asm volatile("cp.async.commit_group;" ::: "memory")
#define CP_WAIT(n)   asm volatile("cp.async.wait_group %0;" :: "n"(n) : "memory")

__device__ __forceinline__ void ldm_x4(uint32_t& r0, uint32_t& r1,
                                       uint32_t& r2, uint32_t& r3, uint32_t addr) {
    asm volatile("ldmatrix.sync.aligned.m8n8.x4.shared.b16 {%0,%1,%2,%3}, [%4];"
                 : "=r"(r0), "=r"(r1), "=r"(r2), "=r"(r3) : "r"(addr));
}
__device__ __forceinline__ void ldm_x2(uint32_t& r0, uint32_t& r1, uint32_t addr) {
    asm volatile("ldmatrix.sync.aligned.m8n8.x2.shared.b16 {%0,%1}, [%2];"
                 : "=r"(r0), "=r"(r1) : "r"(addr));
}
__device__ __forceinline__ void mma16816(float* c, const uint32_t* a, const uint32_t* b) {
    asm volatile("mma.sync.aligned.m16n8k16.row.col.f32.bf16.bf16.f32 "
                 "{%0,%1,%2,%3}, {%4,%5,%6,%7}, {%8,%9}, {%0,%1,%2,%3};"
                 : "+f"(c[0]), "+f"(c[1]), "+f"(c[2]), "+f"(c[3])
                 : "r"(a[0]), "r"(a[1]), "r"(a[2]), "r"(a[3]),
                   "r"(b[0]), "r"(b[1]));
}

// ---------------- integer limb extraction (proven exact) --------------------
__device__ __forceinline__ void limbs_of(float a, float qs,
                                         float& A0, float& A1, float& A2) {
    const float q = a * qs;
    A0 = rintf(q);
    const float r1 = q - A0;
    const float t1 = r1 * 256.0f;
    A1 = rintf(t1);
    const float r2 = t1 - A1;
    A2 = rintf(r2 * 256.0f);
}

// Row converter. Group-major p1: group g at columns [g*K0P, (g+1)*K0P).
// A-side groups: [L0, L1, L1, L0, L2]; B-side: [L1, L0, L1, L2, L0]
//   -> products per group: L0*L1, L1*L0, L1*L1, L0*L2, L2*L0 (same set as
//      the proven interleaved scheme; only the K summation order changes).
template<int KD, int K0P, bool ISA>
__device__ void conv_row_body(const float* __restrict__ gsrc, int valid,
                              __nv_bfloat16* __restrict__ p0,
                              __nv_bfloat16* __restrict__ p1,
                              float* __restrict__ sarr, int ridx,
                              float* __restrict__ srow, float* __restrict__ red) {
    const int tid = threadIdx.x;  // 256
    float mx = 0.0f;
    for (int k = tid; k < KD; k += 256) {
        const float a = valid ? gsrc[k] : 0.0f;
        srow[k] = a;
        mx = fmaxf(mx, fabsf(a));
    }
    red[tid] = mx;
    __syncthreads();
    for (int s = 128; s; s >>= 1) {
        if (tid < s) red[tid] = fmaxf(red[tid], red[tid + s]);
        __syncthreads();
    }
    const float rm = red[0];
    int e = 0;
    if (rm > 0.0f) frexpf(rm, &e);
    if (tid == 0) sarr[ridx] = ldexpf(1.0f, e - 8);
    const float qs = ldexpf(1.0f, 8 - e);
    const float s0 = ldexpf(1.0f, e - 8);
    const float s1 = ldexpf(1.0f, e - 16);
    const float s2 = ldexpf(1.0f, e - 24);

    const __nv_bfloat16 z = __float2bfloat16(0.0f);
    for (int k = tid; k < K0P; k += 256) {
        if (k < KD) {
            float A0, A1, A2;
            limbs_of(srow[k], qs, A0, A1, A2);          // ONCE per element
            p0[k] = __float2bfloat16(A0);
            const __nv_bfloat16 L0 = __float2bfloat16(A0 * s0);
            const __nv_bfloat16 L1 = __float2bfloat16(A1 * s1);
            const __nv_bfloat16 L2 = __float2bfloat16(A2 * s2);
            if (ISA) {
                p1[0 * K0P + k] = L0; p1[1 * K0P + k] = L1;
                p1[2 * K0P + k] = L1; p1[3 * K0P + k] = L0;
                p1[4 * K0P + k] = L2;
            } else {
                p1[0 * K0P + k] = L1; p1[1 * K0P + k] = L0;
                p1[2 * K0P + k] = L1; p1[3 * K0P + k] = L2;
                p1[4 * K0P + k] = L0;
            }
        } else {
            p0[k] = z;
#pragma unroll
            for (int g = 0; g < 5; g++) p1[g * K0P + k] = z;
        }
    }
}

// Merged input conversions: x rows, w1 rows, w2 rows, + cf[] block.
__global__ void __launch_bounds__(256)
k_convIn(const float* __restrict__ x, const float* __restrict__ w1,
         const float* __restrict__ w2) {
    __shared__ float srow[IN_];
    __shared__ float red[256];
    const int b = blockIdx.x;
    if (b < B_) {
        conv_row_body<IN_, K0P1, true>(x + (long)b * IN_, 1,
            g_p0a1 + (long)b * K0P1, g_p1a1 + (long)b * K1P1, g_sa1, b, srow, red);
    } else if (b < B_ + NP) {
        const int n = b - B_;
        conv_row_body<IN_, K0P1, false>(w1 + (long)n * IN_, n < H1,
            g_p0w1 + (long)n * K0P1, g_p1w1 + (long)n * K1P1, g_sw1, n, srow, red);
    } else if (b < B_ + 2 * NP) {
        const int n = b - B_ - NP;
        conv_row_body<H1, K0P2, false>(w2 + (long)n * H1, n < H1,
            g_p0w2 + (long)n * K0P2, g_p1w2 + (long)n * K1P2, g_sw2, n, srow, red);
    } else {
        if (threadIdx.x < T_) {        // cf[] in fp64 closed form
            const double r = 0.77880078307140487;   // exp(-1/4)
            const double q = 0.36787944117144233;   // exp(-1)
            const double tp1 = (double)(threadIdx.x + 1);
            const double rp = exp(-0.25 * tp1);
            const double qp = exp(-tp1);
            const double c = (r * (1.0 - rp) / (1.0 - r)
                            - q * (1.0 - qp) / (1.0 - q)) / (r - q);
            g_cf[threadIdx.x] = (float)c;
        }
    }
}

__global__ void __launch_bounds__(256) k_cA2() {
    __shared__ float srow[H1];
    __shared__ float red[256];
    const int m = blockIdx.x;
    conv_row_body<H1, K0P2, true>(g_h + (long)m * H1, 1,
        g_p0a2 + (long)m * K0P2, g_p1a2 + (long)m * K1P2, g_sa2, m, srow, red);
}

// ---------------- HMMA pass: R11 structure + compile-time dims + tail fix ---
__device__ __forceinline__ void issue_chunk(const __nv_bfloat16* __restrict__ Ag,
                                            const __nv_bfloat16* __restrict__ Bg,
                                            int KPE, int m0, int n0, int c,
                                            uint32_t stage_base, int tid) {
#pragma unroll
    for (int i = 0; i < 2; i++) {
        const int e = tid + 256 * i;           // 0..511
        const int row = e >> 3, c8 = e & 7;
        const uint32_t dst = SW128((uint32_t)(row * 128 + c8 * 16));
        cp_async16(stage_base + dst,
                   Ag + (long)(m0 + row) * KPE + (long)c * 64 + c8 * 8);
        cp_async16(stage_base + 8192 + dst,
                   Bg + (long)(n0 + row) * KPE + (long)c * 64 + c8 * 8);
    }
}

template<int KPE, int NC>
__device__ __forceinline__ void gemm_pass(const __nv_bfloat16* __restrict__ Ag,
                                          const __nv_bfloat16* __restrict__ Bg,
                                          int m0, int n0,
                                          int wm, int wn, int lane, int tid,
                                          uint32_t smb, float* accS /*16*/) {
    issue_chunk(Ag, Bg, KPE, m0, n0, 0, smb, tid);
    CP_COMMIT();
    issue_chunk(Ag, Bg, KPE, m0, n0, 1, smb + 16384, tid);
    CP_COMMIT();

    for (int c = 0; c < NC; c++) {
        // tail-race fix: last chunk's group is the newest committed one, so
        // WAIT(1) would NOT cover it — use WAIT(0) there.
        if (c + 1 < NC) { CP_WAIT(1); } else { CP_WAIT(0); }
        __syncthreads();
        if (c + 2 < NC) {
            issue_chunk(Ag, Bg, KPE, m0, n0, c + 2,
                        smb + ((c + 2) % 3) * 16384, tid);
            CP_COMMIT();
        }
        const uint32_t sA = smb + (c % 3) * 16384;
        const uint32_t sB = sA + 8192;

        float acc[4][4];
#pragma unroll
        for (int b = 0; b < 4; b++)
#pragma unroll
            for (int e2 = 0; e2 < 4; e2++) acc[b][e2] = 0.0f;

#pragma unroll
        for (int k16 = 0; k16 < 4; k16++) {
            uint32_t af[4], bf[4][2];
            const int rowa = wm * 16 + (lane & 15);
            const uint32_t kcol = (uint32_t)(k16 * 32 + (lane >> 4) * 16);
            ldm_x4(af[0], af[1], af[2], af[3],
                   sA + SW128((uint32_t)(rowa * 128) + kcol));
            const uint32_t kcolb = (uint32_t)(k16 * 32 + ((lane >> 3) & 1) * 16);
#pragma unroll
            for (int nt = 0; nt < 4; nt++) {
                const int rowb = wn * 32 + nt * 8 + (lane & 7);
                ldm_x2(bf[nt][0], bf[nt][1],
                       sB + SW128((uint32_t)(rowb * 128) + kcolb));
            }
#pragma unroll
            for (int nt = 0; nt < 4; nt++)
                mma16816(acc[nt], af, bf[nt]);
        }
#pragma unroll
        for (int b = 0; b < 4; b++)
#pragma unroll
            for (int e2 = 0; e2 < 4; e2++)
                accS[b * 4 + e2] = __fadd_rn(accS[b * 4 + e2], acc[b][e2]);
    }
    __syncthreads();   // smem safe for next pass
}

// MODE 1: layer1 (relu -> g_h), MODE 2: layer2 (sigmoid -> g_drive)
template<int MODE>
__global__ void __launch_bounds__(256) k_mma(const float* __restrict__ bias) {
    __shared__ __align__(128) char sm[3][16384];   // 48 KB, 3 stages
    const int tid = threadIdx.x;                   // 256
    const int warp = tid >> 5, lane = tid & 31;
    const int wm = warp & 3, wn = warp >> 2;       // 4 M-warps x 2 N-warps
    const int m0 = blockIdx.y * 64, n0 = blockIdx.x * 64;

    float S0[16], S1[16];
#pragma unroll
    for (int i = 0; i < 16; i++) { S0[i] = 0.0f; S1[i] = 0.0f; }

    const uint32_t smb = smem_u32(sm);
    const float *sa, *sw;
    if (MODE == 1) {
        gemm_pass<K0P1, 13>(g_p0a1, g_p0w1, m0, n0, wm, wn, lane, tid, smb, S0);
        gemm_pass<K1P1, 65>(g_p1a1, g_p1w1, m0, n0, wm, wn, lane, tid, smb, S1);
        sa = g_sa1; sw = g_sw1;
    } else {
        gemm_pass<K0P2,  8>(g_p0a2, g_p0w2, m0, n0, wm, wn, lane, tid, smb, S0);
        gemm_pass<K1P2, 40>(g_p1a2, g_p1w2, m0, n0, wm, wn, lane, tid, smb, S1);
        sa = g_sa2; sw = g_sw2;
    }

    // epilogue: v = RN(S0 * 2^(ea+eb-16)) + S1 + bias (pow2 scale mul exact)
#pragma unroll
    for (int nt = 0; nt < 4; nt++) {
        const int gn = n0 + wn * 32 + nt * 8 + (lane & 3) * 2;
#pragma unroll
        for (int rr = 0; rr < 2; rr++) {
            const int m = m0 + wm * 16 + (lane >> 2) + rr * 8;
            const float sam = sa[m];
#pragma unroll
            for (int jj = 0; jj < 2; jj++) {
                const int n = gn + jj;
                if (n >= H1) continue;
                const float sab = sam * sw[n];
                const int idx = nt * 4 + rr * 2 + jj;
                float v = __fadd_rn(__fmul_rn(S0[idx], sab), S1[idx]);
                v = v + bias[n];
                if (MODE == 1) {
                    g_h[(long)m * H1 + n] = fmaxf(v, 0.0f);
                } else {
                    if (v >= 0.0f) v = 1.0f / (1.0f + expf(-v));
                    else { const float e = expf(v); v = e / (1.0f + e); }
                    g_drive[(long)m * H1 + n] = v;
                }
            }
        }
    }
}

// ---------------- fused gemm3 + LIF scan (proven exact) ----------------
__global__ void __launch_bounds__(256, 8)
k_fused3(const float* __restrict__ w3,
         const float* __restrict__ b3,
         float* __restrict__ out) {
    const int m = blockIdx.x;
    __shared__ float row[H1];
    __shared__ float part[250];
    __shared__ float cf[T_];
    __shared__ unsigned sbits[NOUT][4];

    const int tid = threadIdx.x;  // 256
    for (int k = tid; k < H1; k += 256) row[k] = g_drive[m * H1 + k];
    if (tid < T_) cf[tid] = g_cf[tid];
    __syncthreads();

    if (tid < 250) {
        const int n = tid / 25;
        const int ks = (tid % 25) * 20;
        float s = 0.0f;
#pragma unroll
        for (int k = 0; k < 20; k++)
            s = fmaf(row[ks + k], w3[n * H1 + ks + k], s);
        part[tid] = s;
    }
    __syncthreads();

    if (tid < NOUT) {
        float u = 0.0f;
#pragma unroll
        for (int p = 0; p < 25; p++) u += part[tid * 25 + p];

        const float bb = b3[tid];
        const int SIGB = __float_as_int(0.77880078307140487f);
        float v = 0.0f;
        float f = __int_as_float(SIGB);
        unsigned sb0 = 0, sb1 = 0, sb2 = 0, sb3v = 0;
#pragma unroll
        for (int t = 0; t < T_; t++) {
            const float cur = __fadd_rn(__fmul_rn(cf[t], u), bb);
            v = __fadd_rn(__fmul_rn(f, v), cur);
            const int tb = __float_as_int(__fadd_rn(v, -1.0f));
            const int smask = tb >> 31;
            f = __int_as_float(SIGB & smask);
            const unsigned bit = (unsigned)(~smask) & 1u;
            if (t < 32)       sb0 |= bit << t;
            else if (t < 64)  sb1 |= bit << (t - 32);
            else if (t < 96)  sb2 |= bit << (t - 64);
            else              sb3v |= bit << (t - 96);
        }
        sbits[tid][0] = sb0; sbits[tid][1] = sb1;
        sbits[tid][2] = sb2; sbits[tid][3] = sb3v;
    }
    __syncthreads();

    float* oblk = out + (size_t)m * NOUT * T_;
#pragma unroll
    for (int i = tid; i < NOUT * T_; i += 256) {
        const int n = i / T_;
        const int t = i - n * T_;
        const unsigned w = sbits[n][t >> 5];
        oblk[i] = (float)((w >> (t & 31)) & 1u);
    }
}

// ---------------- launch ----------------
extern "C" void kernel_launch(void* const* d_in, const int* in_sizes, int n_in,
                              void* d_out, int out_size) {
    const float* x  = (const float*)d_in[0];
    const float* w1 = (const float*)d_in[1];
    const float* b1 = (const float*)d_in[2];
    const float* w2 = (const float*)d_in[3];
    const float* b2 = (const float*)d_in[4];
    const float* w3 = (const float*)d_in[5];
    const float* b3 = (const float*)d_in[6];
    float* out = (float*)d_out;

    k_convIn<<<B_ + 2 * NP + 1, 256>>>(x, w1, w2);

    dim3 grid(NP / 64, B_ / 64);               // (8, 16) = 128 CTAs
    k_mma<1><<<grid, 256>>>(b1);
    k_cA2<<<B_, 256>>>();
    k_mma<2><<<grid, 256>>>(b2);

    k_fused3<<<B_, 256>>>(w3, b3, out);
}